// round 9
// baseline (speedup 1.0000x reference)
#include <cuda_runtime.h>

#define NCOLS 32768
#define TPB   512
#define F4PT  16            // float4 per thread (16*4 = 64 floats)
#define KSEL  32
#define CAP   1536          // compact candidate list capacity (mean 747)
#define EQCAP 64
#define FLOORV 2.0f

__device__ __forceinline__ unsigned fkey(float f) {
    unsigned u = __float_as_uint(f);
    return u ^ ((u >> 31) ? 0xFFFFFFFFu : 0x80000000u);
}
__device__ __forceinline__ float keyf(unsigned k) {
    unsigned u = (k & 0x80000000u) ? (k ^ 0x80000000u) : ~k;
    return __uint_as_float(u);
}

__global__ void __launch_bounds__(TPB, 3)
topk_persist(const float* __restrict__ x, float* __restrict__ out, int nrows) {
    __shared__ unsigned cand_meta[CAP];       // 6 KB: (bin<<24)|idx  (fallback: eq idx list)
    __shared__ float    cand_val[CAP];        // 6 KB
    __shared__ unsigned hist[256];
    __shared__ unsigned scn[257];             // fallback only
    __shared__ int      flagS;
    __shared__ unsigned ccnt, eq_cnt;
    __shared__ int      eq_idx[EQCAP];
    __shared__ unsigned eq_key[EQCAP];
    __shared__ unsigned sh_cut, sh_above;
    __shared__ unsigned sh_bin, sh_need, fb_eqc;

    const int t = threadIdx.x;

    for (int row = blockIdx.x; row < nrows; row += gridDim.x) {
        const float* __restrict__ xrow = x + (size_t)row * NCOLS;
        float* __restrict__ orow = out + (size_t)row * NCOLS;
        const float4* __restrict__ xin4 = (const float4*)xrow;
        float4* __restrict__ xo4 = (float4*)orow;

        if (t == 0) { flagS = 0; ccnt = 0u; eq_cnt = 0u; }
        if (t < 256) hist[t] = 0u;
        __syncthreads();                                     // [bar 1]

        // ===== PHASE 1: streaming pass, 4-deep load batches, 1 atomic/candidate =====
        const float4 z4 = make_float4(0.f, 0.f, 0.f, 0.f);
#pragma unroll
        for (int jb = 0; jb < F4PT / 4; jb++) {
            float4 v[4];
#pragma unroll
            for (int u = 0; u < 4; u++)                       // 4 back-to-back LDG.128
                v[u] = __ldcs(&xin4[t + (jb * 4 + u) * TPB]);
#pragma unroll
            for (int u = 0; u < 4; u++)                       // 4 back-to-back STG.128
                __stcs(&xo4[t + (jb * 4 + u) * TPB], z4);
#pragma unroll
            for (int u = 0; u < 4; u++) {
                float m = fmaxf(fmaxf(v[u].x, v[u].y), fmaxf(v[u].z, v[u].w));
                if (m >= FLOORV) {                            // rare (~9%)
                    const int base = (t + (jb * 4 + u) * TPB) * 4;
                    const float* fp = (const float*)&v[u];
#pragma unroll
                    for (int c = 0; c < 4; c++) {
                        float f = fp[c];
                        if (f >= FLOORV) {
                            unsigned ub = __float_as_uint(f);
                            unsigned bin = (ub >> 16) - 0x4000u;
                            bin = (bin > 255u) ? 255u : bin;
                            unsigned pos = atomicAdd(&ccnt, 1u);
                            if (pos < CAP) {
                                cand_meta[pos] = (bin << 24) | (unsigned)(base + c);
                                cand_val[pos]  = f;
                            } else {
                                flagS = 1;
                            }
                        }
                    }
                }
            }
        }
        __syncthreads();                                     // [bar 2]

        // ===== PHASE 2a: histogram from compact list =====
        const int ncand = (ccnt < CAP) ? (int)ccnt : CAP;
        if (!flagS) {
            for (int i = t; i < ncand; i += TPB)
                atomicAdd(&hist[cand_meta[i] >> 24], 1u);
        }
        __syncthreads();                                     // [bar 3]

        // ===== PHASE 2b: warp-0 suffix scan over 256 bins =====
        if (t < 32) {
            unsigned h[8], tot = 0u;
#pragma unroll
            for (int c = 0; c < 8; c++) { h[c] = hist[t * 8 + c]; tot += h[c]; }
            unsigned v = tot;
#pragma unroll
            for (int off = 1; off < 32; off <<= 1) {
                unsigned o = __shfl_down_sync(0xFFFFFFFFu, v, off);
                if (t + off < 32) v += o;
            }
            unsigned nxt = v - tot;
#pragma unroll
            for (int c = 7; c >= 0; c--) {
                unsigned s = nxt + h[c];
                if (s >= KSEL && nxt < KSEL) { sh_cut = (unsigned)(t * 8 + c); sh_above = nxt; }
                nxt = s;
            }
            if (t == 0 && v < KSEL) flagS = 1;
        }
        __syncthreads();                                     // [bar 4]

        // ===== PHASE 3: fast-path writes from shared =====
        if (!flagS) {
            const unsigned cut = sh_cut;
            for (int i = t; i < ncand; i += TPB) {
                const unsigned meta = cand_meta[i];
                const unsigned bin = meta >> 24;
                const int idx = (int)(meta & 0xFFFFFFu);
                const float f = cand_val[i];
                if (bin > cut) {
                    orow[idx] = f;                            // winner, f > 0 (relu identity)
                } else if (bin == cut) {
                    unsigned p = atomicAdd(&eq_cnt, 1u);
                    if (p < EQCAP) { eq_idx[p] = idx; eq_key[p] = __float_as_uint(f); }
                    else flagS = 1;
                }
            }
        }
        __syncthreads();                                     // [bar 5]

        if (!flagS) {
            // exact rank inside the cut bin: (value desc, index asc)
            const unsigned m = eq_cnt;
            const unsigned need = KSEL - sh_above;
            if (t < (int)m) {
                unsigned u = eq_key[t];
                int idx = eq_idx[t];
                unsigned r = 0;
                for (unsigned j = 0; j < m; j++) {
                    unsigned uj = eq_key[j];
                    if (uj > u || (uj == u && eq_idx[j] < idx)) r++;
                }
                if (r < need) orow[idx] = __uint_as_float(u);
            }
        } else {
            // ===== EXACT FALLBACK (uniform branch; never taken for bench input) =====
            unsigned prefix = 0, needv = KSEL;
#pragma unroll 1
            for (int p = 0; p < 4; p++) {
                const int shift = 24 - 8 * p;
                if (t < 256) hist[t] = 0u;
                __syncthreads();
                const unsigned hiMask = (p == 0) ? 0u : (0xFFFFFFFFu << (shift + 8));
#pragma unroll 1
                for (int j = t; j < NCOLS; j += TPB) {
                    unsigned k = fkey(xrow[j]);
                    if ((k & hiMask) == prefix)
                        atomicAdd(&hist[(k >> shift) & 255u], 1u);
                }
                __syncthreads();
                if (t < 256) scn[t] = hist[t];
                if (t == 0) scn[256] = 0u;
                __syncthreads();
                for (int off = 1; off < 256; off <<= 1) {
                    unsigned a = (t < 256 && t + off < 256) ? scn[t + off] : 0u;
                    __syncthreads();
                    if (t < 256) scn[t] += a;
                    __syncthreads();
                }
                if (t < 256) {
                    if (scn[t] >= needv && scn[t + 1] < needv) {
                        sh_bin = (unsigned)t; sh_need = needv - scn[t + 1];
                    }
                }
                __syncthreads();
                prefix |= sh_bin << shift;
                needv = sh_need;
                __syncthreads();
            }
            const unsigned T = prefix;
            const unsigned need_eq = needv;
            if (t == 0) fb_eqc = 0u;
            __syncthreads();
#pragma unroll 1
            for (int j = t; j < NCOLS; j += TPB) {
                float f = xrow[j];
                unsigned k = fkey(f);
                if (k > T) {
                    orow[j] = fmaxf(f, 0.0f);
                } else if (k == T) {
                    unsigned p = atomicAdd(&fb_eqc, 1u);
                    if (p < CAP) cand_meta[p] = (unsigned)j;
                }
            }
            __syncthreads();
            if (t == 0) {
                const float tv = fmaxf(keyf(T), 0.0f);
                unsigned n = fb_eqc;
                if (n <= CAP) {
                    int nn = (int)n;
                    for (unsigned s = 0; s < need_eq; s++) {
                        unsigned best = 0xFFFFFFFFu; int bi = -1;
                        for (int i = 0; i < nn; i++) {
                            unsigned idx = cand_meta[i];
                            if (idx < best) { best = idx; bi = i; }
                        }
                        if (bi >= 0) { cand_meta[bi] = 0xFFFFFFFFu; orow[best] = tv; }
                    }
                } else {
                    unsigned w = 0;
                    for (int idx = 0; idx < NCOLS && w < need_eq; idx++) {
                        if (fkey(xrow[idx]) == T) { orow[idx] = tv; w++; }
                    }
                }
            }
        }
        __syncthreads();                                     // [bar 6] end-of-row
    }
}

extern "C" void kernel_launch(void* const* d_in, const int* in_sizes, int n_in,
                              void* d_out, int out_size) {
    const float* x = (const float*)d_in[0];
    float* out = (float*)d_out;
    const int rows = in_sizes[0] / NCOLS;
    int sms = 148;
    cudaDeviceGetAttribute(&sms, cudaDevAttrMultiProcessorCount, 0);
    int grid = sms * 3;                     // exactly one full wave of resident CTAs
    if (grid > rows) grid = rows;
    topk_persist<<<grid, TPB>>>(x, out, rows);
}

// round 11
// speedup vs baseline: 1.0947x; 1.0947x over previous
#include <cuda_runtime.h>

#define NCOLS 32768
#define TPB   512
#define F4PT  16            // float4 per thread (16*4 = 64 floats)
#define KSEL  32
#define SLOTS 10
#define EQCAP 64
#define FLOORV 2.0f
#define FBCAP (TPB * SLOTS)

__device__ __forceinline__ unsigned fkey(float f) {
    unsigned u = __float_as_uint(f);
    return u ^ ((u >> 31) ? 0xFFFFFFFFu : 0x80000000u);
}
__device__ __forceinline__ float keyf(unsigned k) {
    unsigned u = (k & 0x80000000u) ? (k ^ 0x80000000u) : ~k;
    return __uint_as_float(u);
}

__global__ void __launch_bounds__(TPB, 3)
topk_kernel(const float* __restrict__ x, float* __restrict__ out) {
    __shared__ uint2    slot2[TPB * SLOTS];   // 40 KB: (valbits, idx) per-thread private
    __shared__ unsigned hist[256];
    __shared__ unsigned scn[257];             // fallback only
    __shared__ int      flagS;
    __shared__ unsigned eq_cnt;
    __shared__ int      eq_idx[EQCAP];
    __shared__ unsigned eq_key[EQCAP];
    __shared__ unsigned sh_cut, sh_above;
    __shared__ unsigned sh_bin, sh_need, fb_eqc;

    const int row = blockIdx.x;
    const int t = threadIdx.x;
    const float* __restrict__ xrow = x + (size_t)row * NCOLS;
    float* __restrict__ orow = out + (size_t)row * NCOLS;
    const float4* __restrict__ xin4 = (const float4*)xrow;
    float4* __restrict__ xo4 = (float4*)orow;

    if (t == 0) { flagS = 0; eq_cnt = 0u; }
    if (t < 256) hist[t] = 0u;
    __syncthreads();                                         // [bar 1]

    // ===== PHASE 1: streaming pass, 4-deep load batches, fused histogram =====
    int cnt = 0;
    const int slotbase = t * SLOTS;
    const float4 z4 = make_float4(0.f, 0.f, 0.f, 0.f);
#pragma unroll
    for (int jb = 0; jb < F4PT / 4; jb++) {
        float4 v[4];
#pragma unroll
        for (int u = 0; u < 4; u++)                           // 4 back-to-back LDG.128
            v[u] = __ldcs(&xin4[t + (jb * 4 + u) * TPB]);
#pragma unroll
        for (int u = 0; u < 4; u++)                           // 4 back-to-back STG.128
            __stcs(&xo4[t + (jb * 4 + u) * TPB], z4);
#pragma unroll
        for (int u = 0; u < 4; u++) {
            float m = fmaxf(fmaxf(v[u].x, v[u].y), fmaxf(v[u].z, v[u].w));
            if (m >= FLOORV) {                                // rare (~9% of threads/iter)
                const int base = (t + (jb * 4 + u) * TPB) * 4;
                const float* fp = (const float*)&v[u];
#pragma unroll
                for (int c = 0; c < 4; c++) {
                    float f = fp[c];
                    if (f >= FLOORV) {
                        unsigned ub = __float_as_uint(f);
                        unsigned bin = (ub >> 16) - 0x4000u;  // positive floats: bits monotone
                        bin = (bin > 255u) ? 255u : bin;
                        atomicAdd(&hist[bin], 1u);
                        if (cnt < SLOTS)
                            slot2[slotbase + cnt] = make_uint2(ub, (unsigned)(base + c));
                        cnt++;
                    }
                }
            }
        }
    }
    if (cnt > SLOTS) flagS = 1;                               // overflow -> exact fallback
    const int myn = (cnt < SLOTS) ? cnt : SLOTS;
    __syncthreads();                                         // [bar 2]

    // ===== PHASE 2: slot prefetch (all warps) overlapped with warp-0 scan =====
    uint2 lc[SLOTS];
#pragma unroll
    for (int i = 0; i < SLOTS; i++)                           // unconditional, own region,
        lc[i] = slot2[slotbase + i];                          // independent LDS.64s

    if (t < 32) {
        unsigned h[8], tot = 0u;
#pragma unroll
        for (int c = 0; c < 8; c++) { h[c] = hist[t * 8 + c]; tot += h[c]; }
        unsigned v = tot;
#pragma unroll
        for (int off = 1; off < 32; off <<= 1) {
            unsigned o = __shfl_down_sync(0xFFFFFFFFu, v, off);
            if (t + off < 32) v += o;
        }
        unsigned nxt = v - tot;
#pragma unroll
        for (int c = 7; c >= 0; c--) {
            unsigned s = nxt + h[c];
            if (s >= KSEL && nxt < KSEL) { sh_cut = (unsigned)(t * 8 + c); sh_above = nxt; }
            nxt = s;
        }
        if (t == 0 && v < KSEL) flagS = 1;                    // too few candidates -> fallback
    }
    __syncthreads();                                         // [bar 3]

    // ===== PHASE 3: writes from registers — no dependent LDS chain =====
    if (!flagS) {
        const unsigned cut = sh_cut;
#pragma unroll
        for (int i = 0; i < SLOTS; i++) {
            if (i < myn) {
                const unsigned ub = lc[i].x;
                const int idx = (int)lc[i].y;
                unsigned bin = (ub >> 16) - 0x4000u;
                bin = (bin > 255u) ? 255u : bin;
                if (bin > cut) {
                    orow[idx] = __uint_as_float(ub);          // winner, > 0 (relu identity)
                } else if (bin == cut) {
                    unsigned p = atomicAdd(&eq_cnt, 1u);
                    if (p < EQCAP) { eq_idx[p] = idx; eq_key[p] = ub; }
                    else flagS = 1;
                }
            }
        }
    }
    __syncthreads();                                         // [bar 4]

    if (!flagS) {
        // exact rank inside the cut bin: (value desc, index asc)
        const unsigned m = eq_cnt;
        const unsigned need = KSEL - sh_above;
        if (t < (int)m) {
            unsigned u = eq_key[t];
            int idx = eq_idx[t];
            unsigned r = 0;
            for (unsigned j = 0; j < m; j++) {
                unsigned uj = eq_key[j];
                if (uj > u || (uj == u && eq_idx[j] < idx)) r++;
            }
            if (r < need) orow[idx] = __uint_as_float(u);
        }
        return;
    }

    // ===== EXACT FALLBACK (never taken for bench input) =====
    unsigned* fbl = (unsigned*)slot2;                         // scratch reuse
    unsigned prefix = 0, needv = KSEL;
#pragma unroll 1
    for (int p = 0; p < 4; p++) {
        const int shift = 24 - 8 * p;
        if (t < 256) hist[t] = 0u;
        __syncthreads();
        const unsigned hiMask = (p == 0) ? 0u : (0xFFFFFFFFu << (shift + 8));
#pragma unroll 1
        for (int j = 0; j < F4PT; j++) {
            float4 v = xin4[t + j * TPB];
            const float* fv = (const float*)&v;
            for (int c = 0; c < 4; c++) {
                unsigned k = fkey(fv[c]);
                if ((k & hiMask) == prefix)
                    atomicAdd(&hist[(k >> shift) & 255u], 1u);
            }
        }
        __syncthreads();
        if (t < 256) scn[t] = hist[t];
        if (t == 0) scn[256] = 0u;
        __syncthreads();
        for (int off = 1; off < 256; off <<= 1) {
            unsigned a = (t < 256 && t + off < 256) ? scn[t + off] : 0u;
            __syncthreads();
            if (t < 256) scn[t] += a;
            __syncthreads();
        }
        if (t < 256) {
            if (scn[t] >= needv && scn[t + 1] < needv) {
                sh_bin = (unsigned)t; sh_need = needv - scn[t + 1];
            }
        }
        __syncthreads();
        prefix |= sh_bin << shift;
        needv = sh_need;
        __syncthreads();
    }
    const unsigned T = prefix;
    const unsigned need_eq = needv;
    if (t == 0) fb_eqc = 0u;
    __syncthreads();
#pragma unroll 1
    for (int j = 0; j < F4PT; j++) {
        float4 v = xin4[t + j * TPB];
        const float* fv = (const float*)&v;
        int base = (t + j * TPB) * 4;
        for (int c = 0; c < 4; c++) {
            unsigned k = fkey(fv[c]);
            if (k > T) {
                orow[base + c] = fmaxf(fv[c], 0.0f);
            } else if (k == T) {
                unsigned p = atomicAdd(&fb_eqc, 1u);
                if (p < FBCAP) fbl[p] = (unsigned)(base + c);
            }
        }
    }
    __syncthreads();
    if (t == 0) {
        const float tv = fmaxf(keyf(T), 0.0f);
        unsigned n = fb_eqc;
        if (n <= FBCAP) {
            int nn = (int)n;
            for (unsigned s = 0; s < need_eq; s++) {
                unsigned best = 0xFFFFFFFFu; int bi = -1;
                for (int i = 0; i < nn; i++) {
                    unsigned idx = fbl[i];
                    if (idx < best) { best = idx; bi = i; }
                }
                if (bi >= 0) { fbl[bi] = 0xFFFFFFFFu; orow[best] = tv; }
            }
        } else {
            unsigned w = 0;
            for (int idx = 0; idx < NCOLS && w < need_eq; idx++) {
                if (fkey(xrow[idx]) == T) { orow[idx] = tv; w++; }
            }
        }
    }
}

extern "C" void kernel_launch(void* const* d_in, const int* in_sizes, int n_in,
                              void* d_out, int out_size) {
    const float* x = (const float*)d_in[0];
    float* out = (float*)d_out;
    const int rows = in_sizes[0] / NCOLS;
    topk_kernel<<<rows, TPB>>>(x, out);
}

// round 14
// speedup vs baseline: 1.0959x; 1.0011x over previous
#include <cuda_runtime.h>

#define NCOLS 32768
#define TPB   512
#define F4PT  16            // float4 per thread (16*4 = 64 floats)
#define KSEL  32
#define SLOTS 8
#define EQCAP 64
#define FLOORV 2.5f
#define FBCAP (TPB * SLOTS)

__device__ __forceinline__ unsigned fkey(float f) {
    unsigned u = __float_as_uint(f);
    return u ^ ((u >> 31) ? 0xFFFFFFFFu : 0x80000000u);
}
__device__ __forceinline__ float keyf(unsigned k) {
    unsigned u = (k & 0x80000000u) ? (k ^ 0x80000000u) : ~k;
    return __uint_as_float(u);
}

__global__ void __launch_bounds__(TPB, 3)
topk_kernel(const float* __restrict__ x, float* __restrict__ out) {
    __shared__ uint2    slot2[TPB * SLOTS];   // 32 KB: (valbits, idx) per-thread private
    __shared__ unsigned hist[256];
    __shared__ unsigned scn[257];             // fallback only
    __shared__ int      flagS;
    __shared__ unsigned eq_cnt;
    __shared__ int      eq_idx[EQCAP];
    __shared__ unsigned eq_key[EQCAP];
    __shared__ unsigned sh_bin, sh_need, fb_eqc;

    const int row = blockIdx.x;
    const int t = threadIdx.x;
    const int lane = t & 31;
    const float* __restrict__ xrow = x + (size_t)row * NCOLS;
    float* __restrict__ orow = out + (size_t)row * NCOLS;
    const float4* __restrict__ xin4 = (const float4*)xrow;
    float4* __restrict__ xo4 = (float4*)orow;

    if (t == 0) { flagS = 0; eq_cnt = 0u; }
    if (t < 256) hist[t] = 0u;
    __syncthreads();                                         // [bar 1]

    // ===== PHASE 1: streaming pass, 4-deep load batches, fused histogram =====
    int cnt = 0;
    const int slotbase = t * SLOTS;
    const float4 z4 = make_float4(0.f, 0.f, 0.f, 0.f);
#pragma unroll
    for (int jb = 0; jb < F4PT / 4; jb++) {
        float4 v[4];
#pragma unroll
        for (int u = 0; u < 4; u++)                           // 4 back-to-back LDG.128
            v[u] = __ldcs(&xin4[t + (jb * 4 + u) * TPB]);
#pragma unroll
        for (int u = 0; u < 4; u++)                           // 4 back-to-back STG.128
            __stcs(&xo4[t + (jb * 4 + u) * TPB], z4);
#pragma unroll
        for (int u = 0; u < 4; u++) {
            float m = fmaxf(fmaxf(v[u].x, v[u].y), fmaxf(v[u].z, v[u].w));
            if (m >= FLOORV) {                                // rare (~2.5% of threads/iter)
                const int base = (t + (jb * 4 + u) * TPB) * 4;
                const float* fp = (const float*)&v[u];
#pragma unroll
                for (int c = 0; c < 4; c++) {
                    float f = fp[c];
                    if (f >= FLOORV) {
                        unsigned ub = __float_as_uint(f);
                        unsigned bin = (ub >> 16) - 0x4000u;  // positive floats: bits monotone
                        bin = (bin > 255u) ? 255u : bin;
                        atomicAdd(&hist[bin], 1u);
                        if (cnt < SLOTS)
                            slot2[slotbase + cnt] = make_uint2(ub, (unsigned)(base + c));
                        cnt++;
                    }
                }
            }
        }
    }
    if (cnt > SLOTS) flagS = 1;                               // overflow -> exact fallback
    const int myn = (cnt < SLOTS) ? cnt : SLOTS;
    __syncthreads();                                         // [bar 2] hist+slots frozen

    const int ok_ovf = !flagS;                                // phase-1 overflow state

    // ===== PHASE 2: slot prefetch + REDUNDANT per-warp scan (no barrier) =====
    uint2 lc[SLOTS];
#pragma unroll
    for (int i = 0; i < SLOTS; i++)                           // own region, independent LDS.64
        lc[i] = slot2[slotbase + i];

    unsigned cut = 0, above = 0;
    int ok_scan;
    {
        unsigned h[8], tot = 0u;
#pragma unroll
        for (int c = 0; c < 8; c++) { h[c] = hist[lane * 8 + c]; tot += h[c]; }
        unsigned v = tot;
#pragma unroll
        for (int off = 1; off < 32; off <<= 1) {              // inclusive suffix across lanes
            unsigned o = __shfl_down_sync(0xFFFFFFFFu, v, off);
            if (lane + off < 32) v += o;
        }
        unsigned nxt = v - tot;
        unsigned mycut = 0, myabove = 0;
        int found = 0;
#pragma unroll
        for (int c = 7; c >= 0; c--) {                        // high bin -> low within lane
            unsigned s = nxt + h[c];
            if (s >= KSEL && nxt < KSEL) { mycut = (unsigned)(lane * 8 + c); myabove = nxt; found = 1; }
            nxt = s;
        }
        unsigned bal = __ballot_sync(0xFFFFFFFFu, found);
        ok_scan = (bal != 0u);                                // total >= KSEL iff some lane found
        if (ok_scan) {
            int src = __ffs(bal) - 1;
            cut   = __shfl_sync(0xFFFFFFFFu, mycut,   src);
            above = __shfl_sync(0xFFFFFFFFu, myabove, src);
        } else if (lane == 0) {
            flagS = 1;                                        // benign multi-writer, same value
        }
    }

    // ===== PHASE 3: writes from registers (guarded by register flags only) =====
    if (ok_ovf && ok_scan) {
#pragma unroll
        for (int i = 0; i < SLOTS; i++) {
            if (i < myn) {
                const unsigned ub = lc[i].x;
                const int idx = (int)lc[i].y;
                unsigned bin = (ub >> 16) - 0x4000u;
                bin = (bin > 255u) ? 255u : bin;
                if (bin > cut) {
                    orow[idx] = __uint_as_float(ub);          // winner, > 0 (relu identity)
                } else if (bin == cut) {
                    unsigned p = atomicAdd(&eq_cnt, 1u);
                    if (p < EQCAP) { eq_idx[p] = idx; eq_key[p] = ub; }
                    else flagS = 1;
                }
            }
        }
    }
    __syncthreads();                                         // [bar 3] eq list + flagS final

    if (!flagS) {
        // exact rank inside the cut bin: (value desc, index asc)
        const unsigned m = eq_cnt;
        const unsigned need = KSEL - above;                   // warp-uniform register value
        if (t < (int)m) {
            unsigned u = eq_key[t];
            int idx = eq_idx[t];
            unsigned r = 0;
            for (unsigned j = 0; j < m; j++) {
                unsigned uj = eq_key[j];
                if (uj > u || (uj == u && eq_idx[j] < idx)) r++;
            }
            if (r < need) orow[idx] = __uint_as_float(u);
        }
        return;
    }

    // ===== EXACT FALLBACK (never taken for bench input) =====
    unsigned* fbl = (unsigned*)slot2;                         // scratch reuse
    unsigned prefix = 0, needv = KSEL;
#pragma unroll 1
    for (int p = 0; p < 4; p++) {
        const int shift = 24 - 8 * p;
        if (t < 256) hist[t] = 0u;
        __syncthreads();
        const unsigned hiMask = (p == 0) ? 0u : (0xFFFFFFFFu << (shift + 8));
#pragma unroll 1
        for (int j = 0; j < F4PT; j++) {
            float4 v = xin4[t + j * TPB];
            const float* fv = (const float*)&v;
            for (int c = 0; c < 4; c++) {
                unsigned k = fkey(fv[c]);
                if ((k & hiMask) == prefix)
                    atomicAdd(&hist[(k >> shift) & 255u], 1u);
            }
        }
        __syncthreads();
        if (t < 256) scn[t] = hist[t];
        if (t == 0) scn[256] = 0u;
        __syncthreads();
        for (int off = 1; off < 256; off <<= 1) {
            unsigned a = (t < 256 && t + off < 256) ? scn[t + off] : 0u;
            __syncthreads();
            if (t < 256) scn[t] += a;
            __syncthreads();
        }
        if (t < 256) {
            if (scn[t] >= needv && scn[t + 1] < needv) {
                sh_bin = (unsigned)t; sh_need = needv - scn[t + 1];
            }
        }
        __syncthreads();
        prefix |= sh_bin << shift;
        needv = sh_need;
        __syncthreads();
    }
    const unsigned T = prefix;
    const unsigned need_eq = needv;
    if (t == 0) fb_eqc = 0u;
    __syncthreads();
#pragma unroll 1
    for (int j = 0; j < F4PT; j++) {
        float4 v = xin4[t + j * TPB];
        const float* fv = (const float*)&v;
        int base = (t + j * TPB) * 4;
        for (int c = 0; c < 4; c++) {
            unsigned k = fkey(fv[c]);
            if (k > T) {
                orow[base + c] = fmaxf(fv[c], 0.0f);
            } else if (k == T) {
                unsigned p = atomicAdd(&fb_eqc, 1u);
                if (p < FBCAP) fbl[p] = (unsigned)(base + c);
            }
        }
    }
    __syncthreads();
    if (t == 0) {
        const float tv = fmaxf(keyf(T), 0.0f);
        unsigned n = fb_eqc;
        if (n <= FBCAP) {
            int nn = (int)n;
            for (unsigned s = 0; s < need_eq; s++) {
                unsigned best = 0xFFFFFFFFu; int bi = -1;
                for (int i = 0; i < nn; i++) {
                    unsigned idx = fbl[i];
                    if (idx < best) { best = idx; bi = i; }
                }
                if (bi >= 0) { fbl[bi] = 0xFFFFFFFFu; orow[best] = tv; }
            }
        } else {
            unsigned w = 0;
            for (int idx = 0; idx < NCOLS && w < need_eq; idx++) {
                if (fkey(xrow[idx]) == T) { orow[idx] = tv; w++; }
            }
        }
    }
}

extern "C" void kernel_launch(void* const* d_in, const int* in_sizes, int n_in,
                              void* d_out, int out_size) {
    const float* x = (const float*)d_in[0];
    float* out = (float*)d_out;
    const int rows = in_sizes[0] / NCOLS;
    topk_kernel<<<rows, TPB>>>(x, out);
}